// round 6
// baseline (speedup 1.0000x reference)
#include <cuda_runtime.h>
#include <math.h>

#define S_LEN   2048
#define BATCH   64
#define ISZ     512
#define HSZ     512
#define G3      1536
#define NLAYERS 2

// ---------------- device scratch (no cudaMalloc allowed) ----------------
__device__ float g_xlin[(size_t)S_LEN * BATCH * G3];   // per-layer input projections
__device__ float g_y1[(size_t)S_LEN * BATCH * HSZ];    // layer-0 outputs
__device__ float g_hbuf[2][BATCH * HSZ];               // ping-pong hidden state
// 4 per-group barrier counters, 128B apart (separate L2 lines)
__device__ __align__(128) unsigned int g_ctr[4 * 32];

// ---------------- packed f32x2 helpers ----------------
typedef unsigned long long u64;

__device__ __forceinline__ u64 pk2(float lo, float hi) {
    u64 r; asm("mov.b64 %0, {%1, %2};" : "=l"(r) : "f"(lo), "f"(hi)); return r;
}
__device__ __forceinline__ void fma2(u64& d, u64 a, u64 b) {
    asm("fma.rn.f32x2 %0, %1, %2, %3;" : "=l"(d) : "l"(a), "l"(b), "l"(d));
}
__device__ __forceinline__ float2 upk2(u64 v) {
    float2 r; asm("mov.b64 {%0, %1}, %2;" : "=f"(r.x), "=f"(r.y) : "l"(v)); return r;
}

// ---------------- tf32 helpers ----------------
__device__ __forceinline__ float to_tf32(float x) {
    float r; asm("cvt.rna.tf32.f32 %0, %1;" : "=f"(r) : "f"(x)); return r;
}
__device__ __forceinline__ void mma_tf32(float* d, const unsigned* a, const unsigned* b) {
    asm("mma.sync.aligned.m16n8k8.row.col.f32.tf32.tf32.f32 "
        "{%0,%1,%2,%3}, {%4,%5,%6,%7}, {%8,%9}, {%0,%1,%2,%3};"
        : "+f"(d[0]), "+f"(d[1]), "+f"(d[2]), "+f"(d[3])
        : "r"(a[0]), "r"(a[1]), "r"(a[2]), "r"(a[3]), "r"(b[0]), "r"(b[1]));
}

// =====================================================================
// tf32 tensor-core GEMM: C[M,N] = A[M,K=512] * W[N,K=512]^T + bias[N]
// Block 128x128, 8 warps (2x4), warp tile 64x32, K staged 16, double buffer.
// =====================================================================
#define GBM 128
#define GBN 128
#define GBK 16
#define GSTAGES (ISZ / GBK)   // 32
#define APAD 20               // padded row stride (floats); conflict-free frags

__global__ __launch_bounds__(256) void gemm_xproj_tf32(
    const float* __restrict__ A, const float* __restrict__ W,
    const float* __restrict__ bias, float* __restrict__ C)
{
    __shared__ __align__(16) float As[2][GBM * APAD];
    __shared__ __align__(16) float Bs[2][GBN * APAD];

    const int bx = blockIdx.x;
    const int by = blockIdx.y;
    const int tid  = threadIdx.x;
    const int lane = tid & 31;
    const int wid  = tid >> 5;
    const int wm = wid & 1;
    const int wn = wid >> 1;
    const int g  = lane >> 2;
    const int t4 = lane & 3;

    const int lrow = tid >> 2;
    const int lc4  = (tid & 3) * 4;

    const float* Ab = A + ((size_t)by * GBM + lrow) * ISZ + lc4;
    const float* Wb = W + ((size_t)bx * GBN + lrow) * ISZ + lc4;

    float4 av[2], wv[2];

    av[0] = *(const float4*)(Ab);
    av[1] = *(const float4*)(Ab + (size_t)64 * ISZ);
    wv[0] = *(const float4*)(Wb);
    wv[1] = *(const float4*)(Wb + (size_t)64 * ISZ);
    {
        float* as0 = &As[0][lrow * APAD + lc4];
        float* bs0 = &Bs[0][lrow * APAD + lc4];
        as0[0] = to_tf32(av[0].x); as0[1] = to_tf32(av[0].y);
        as0[2] = to_tf32(av[0].z); as0[3] = to_tf32(av[0].w);
        as0[64 * APAD + 0] = to_tf32(av[1].x); as0[64 * APAD + 1] = to_tf32(av[1].y);
        as0[64 * APAD + 2] = to_tf32(av[1].z); as0[64 * APAD + 3] = to_tf32(av[1].w);
        bs0[0] = to_tf32(wv[0].x); bs0[1] = to_tf32(wv[0].y);
        bs0[2] = to_tf32(wv[0].z); bs0[3] = to_tf32(wv[0].w);
        bs0[64 * APAD + 0] = to_tf32(wv[1].x); bs0[64 * APAD + 1] = to_tf32(wv[1].y);
        bs0[64 * APAD + 2] = to_tf32(wv[1].z); bs0[64 * APAD + 3] = to_tf32(wv[1].w);
    }
    __syncthreads();

    float acc[4][4][4];
#pragma unroll
    for (int i = 0; i < 4; i++)
#pragma unroll
        for (int j = 0; j < 4; j++)
#pragma unroll
            for (int r = 0; r < 4; r++) acc[i][j][r] = 0.f;

    for (int s = 0; s < GSTAGES; s++) {
        const int cur = s & 1;
        if (s + 1 < GSTAGES) {
            const size_t ko = (size_t)(s + 1) * GBK;
            av[0] = *(const float4*)(Ab + ko);
            av[1] = *(const float4*)(Ab + (size_t)64 * ISZ + ko);
            wv[0] = *(const float4*)(Wb + ko);
            wv[1] = *(const float4*)(Wb + (size_t)64 * ISZ + ko);
        }

        const float* as = As[cur];
        const float* bs = Bs[cur];
#pragma unroll
        for (int kk = 0; kk < 2; kk++) {
            const int kb = kk * 8 + t4;
            unsigned af[4][4];
#pragma unroll
            for (int ms = 0; ms < 4; ms++) {
                const int r0 = (wm * 64 + ms * 16 + g) * APAD;
                af[ms][0] = __float_as_uint(as[r0 + kb]);
                af[ms][1] = __float_as_uint(as[r0 + 8 * APAD + kb]);
                af[ms][2] = __float_as_uint(as[r0 + kb + 4]);
                af[ms][3] = __float_as_uint(as[r0 + 8 * APAD + kb + 4]);
            }
#pragma unroll
            for (int ns = 0; ns < 4; ns++) {
                const int c0 = (wn * 32 + ns * 8 + g) * APAD;
                unsigned bf[2];
                bf[0] = __float_as_uint(bs[c0 + kb]);
                bf[1] = __float_as_uint(bs[c0 + kb + 4]);
#pragma unroll
                for (int ms = 0; ms < 4; ms++)
                    mma_tf32(acc[ms][ns], af[ms], bf);
            }
        }

        if (s + 1 < GSTAGES) {
            float* as1 = &As[cur ^ 1][lrow * APAD + lc4];
            float* bs1 = &Bs[cur ^ 1][lrow * APAD + lc4];
            as1[0] = to_tf32(av[0].x); as1[1] = to_tf32(av[0].y);
            as1[2] = to_tf32(av[0].z); as1[3] = to_tf32(av[0].w);
            as1[64 * APAD + 0] = to_tf32(av[1].x); as1[64 * APAD + 1] = to_tf32(av[1].y);
            as1[64 * APAD + 2] = to_tf32(av[1].z); as1[64 * APAD + 3] = to_tf32(av[1].w);
            bs1[0] = to_tf32(wv[0].x); bs1[1] = to_tf32(wv[0].y);
            bs1[2] = to_tf32(wv[0].z); bs1[3] = to_tf32(wv[0].w);
            bs1[64 * APAD + 0] = to_tf32(wv[1].x); bs1[64 * APAD + 1] = to_tf32(wv[1].y);
            bs1[64 * APAD + 2] = to_tf32(wv[1].z); bs1[64 * APAD + 3] = to_tf32(wv[1].w);
        }
        __syncthreads();
    }

    float bv[4][2];
#pragma unroll
    for (int ns = 0; ns < 4; ns++) {
        const int cn = bx * GBN + wn * 32 + ns * 8 + t4 * 2;
        bv[ns][0] = __ldg(&bias[cn]);
        bv[ns][1] = __ldg(&bias[cn + 1]);
    }
#pragma unroll
    for (int ms = 0; ms < 4; ms++) {
        const size_t r0 = (size_t)by * GBM + wm * 64 + ms * 16 + g;
#pragma unroll
        for (int ns = 0; ns < 4; ns++) {
            const int cn = bx * GBN + wn * 32 + ns * 8 + t4 * 2;
            float2 v0 = {acc[ms][ns][0] + bv[ns][0], acc[ms][ns][1] + bv[ns][1]};
            float2 v1 = {acc[ms][ns][2] + bv[ns][0], acc[ms][ns][3] + bv[ns][1]};
            *(float2*)(C + r0 * G3 + cn)       = v0;
            *(float2*)(C + (r0 + 8) * G3 + cn) = v1;
        }
    }
}

// =====================================================================
// Recurrent GRU kernel: persistent, 128 blocks (32 h-chunks x 4 b-chunks).
// Per-group atomic barrier: each bc-group of 32 blocks syncs on its OWN
// counter (separate 128B line). Valid because h only flows within a group
// (block (hc,bc) reads h written exclusively by same-bc blocks), and
// ping-pong h buffers + per-step group barrier prevent 2-step skew.
// Single spinner per block (thread 0) -> no poll storm.
// =====================================================================
#define HC   16
#define BC   16
#define NBLK ((HSZ / HC) * (BATCH / BC))   // 128
#define KSL  32
#define REDS 9

#define SM_HS   0                     // h_s[BC][HSZ]         = 8192
#define SM_RED  (BC * HSZ)            // red[256][3][REDS]    = 6912
#define SM_XL   (SM_RED + 256 * 3 * REDS)   // xl_s[3][256]   = 768
#define SM_BH   (SM_XL + 768)         // bh_s[3][HC]          = 48
#define SM_TOT  (SM_BH + 48)
#define SMEM_BYTES (SM_TOT * 4)

__device__ __forceinline__ void group_bar(int grp, unsigned* epoch)
{
    __syncthreads();
    if (threadIdx.x == 0) {
        __threadfence();                       // release h stores
        atomicAdd(&g_ctr[grp * 32], 1u);       // 32-way contention only
        const unsigned target = (++(*epoch)) * 32u;
        volatile unsigned* p = &g_ctr[grp * 32];
        while (*p < target) { }
        __threadfence();                       // acquire before reading h
    }
    __syncthreads();
}

__global__ __launch_bounds__(256, 1) void gru_recurrent(
    const float* __restrict__ xlin,
    const float* __restrict__ whh,
    const float* __restrict__ bhh,
    const float* __restrict__ hx,
    float* __restrict__ yout,
    float* __restrict__ hfin)
{
    extern __shared__ __align__(16) float sm[];
    float* h_s  = sm + SM_HS;
    float* red  = sm + SM_RED;
    float* xl_s = sm + SM_XL;
    float* bh_s = sm + SM_BH;

    const int blk = blockIdx.x;
    const int hc = blk >> 2;          // 0..31
    const int bc = blk & 3;           // 0..3  (barrier group)
    const int hbase = hc * HC;
    const int bbase = bc * BC;
    const int tid  = threadIdx.x;
    const int j    = tid & 15;
    const int ks   = tid >> 4;
    const int lane = tid & 31;
    const int warp = tid >> 5;

    // W_hh slice into registers, packed pairs
    u64 wr2[KSL / 2], wz2[KSL / 2], wn2[KSL / 2];
    {
        const u64* rowr = (const u64*)(whh + (size_t)(0 * HSZ + hbase + j) * HSZ + ks * KSL);
        const u64* rowz = (const u64*)(whh + (size_t)(1 * HSZ + hbase + j) * HSZ + ks * KSL);
        const u64* rown = (const u64*)(whh + (size_t)(2 * HSZ + hbase + j) * HSZ + ks * KSL);
#pragma unroll
        for (int q = 0; q < KSL / 2; q++) {
            wr2[q] = rowr[q]; wz2[q] = rowz[q]; wn2[q] = rown[q];
        }
    }
    if (tid < HC) {
        bh_s[tid]          = bhh[0 * HSZ + hbase + tid];
        bh_s[HC + tid]     = bhh[1 * HSZ + hbase + tid];
        bh_s[2 * HC + tid] = bhh[2 * HSZ + hbase + tid];
    }

    // init hidden state (buffer 0) for this block's tile
    {
        const int jj = tid >> 4, bb = tid & 15;
        const size_t idx = (size_t)(bbase + bb) * HSZ + hbase + jj;
        g_hbuf[0][idx] = hx[idx];
    }
    unsigned epoch = 0;
    group_bar(bc, &epoch);

    // prefetch x_lin for t=0
    const int pbb = tid >> 4, pjj = tid & 15;
    const float* xpbase = xlin + ((size_t)(bbase + pbb)) * G3 + hbase + pjj;
    float xn[3];
#pragma unroll
    for (int gk = 0; gk < 3; gk++) xn[gk] = __ldg(xpbase + gk * HSZ);

    for (int t = 0; t < S_LEN; t++) {
        // commit prefetched x_lin; stage h
        {
#pragma unroll
            for (int gk = 0; gk < 3; gk++) xl_s[gk * 256 + tid] = xn[gk];

            const float4* src = (const float4*)(g_hbuf[t & 1] + (size_t)bbase * HSZ);
            float4* dst = (float4*)h_s;
#pragma unroll
            for (int r = 0; r < 8; r++)
                dst[tid + 256 * r] = __ldcg(src + tid + 256 * r);
        }
        __syncthreads();

        // matmul partials (FFMA2 over register W_hh)
#pragma unroll 2
        for (int b = 0; b < BC; b++) {
            u64 ar2 = 0ull, az2 = 0ull, an2 = 0ull;
            const ulonglong2* hp = (const ulonglong2*)(h_s + b * HSZ + ks * KSL);
#pragma unroll
            for (int q = 0; q < KSL / 4; q++) {
                ulonglong2 hv = hp[q];
                fma2(ar2, wr2[2*q],     hv.x);
                fma2(az2, wz2[2*q],     hv.x);
                fma2(an2, wn2[2*q],     hv.x);
                fma2(ar2, wr2[2*q + 1], hv.y);
                fma2(az2, wz2[2*q + 1], hv.y);
                fma2(an2, wn2[2*q + 1], hv.y);
            }
            float2 arf = upk2(ar2), azf = upk2(az2), anf = upk2(an2);
            float ar = arf.x + arf.y;
            float az = azf.x + azf.y;
            float an = anf.x + anf.y;
            ar += __shfl_xor_sync(0xffffffffu, ar, 16);
            az += __shfl_xor_sync(0xffffffffu, az, 16);
            an += __shfl_xor_sync(0xffffffffu, an, 16);
            if (lane < 16) {
                float* rb = red + ((b * HC + j) * 3) * REDS + warp;
                rb[0]        = ar;
                rb[REDS]     = az;
                rb[2 * REDS] = an;
            }
        }

        // prefetch x_lin for t+1 (overlaps reduction + barrier)
        if (t + 1 < S_LEN) {
            const float* xp = xpbase + (size_t)(t + 1) * BATCH * G3;
#pragma unroll
            for (int gk = 0; gk < 3; gk++) xn[gk] = __ldg(xp + gk * HSZ);
        }
        __syncthreads();

        // reduce, gates, update
        {
            const int jj = tid & 15;
            const int bb = tid >> 4;
            const float* rb = red + ((bb * HC + jj) * 3) * REDS;
            float hr = 0.f, hz = 0.f, hn = 0.f;
#pragma unroll
            for (int w = 0; w < 8; w++) {
                hr += rb[w]; hz += rb[REDS + w]; hn += rb[2 * REDS + w];
            }
            hr += bh_s[jj]; hz += bh_s[HC + jj]; hn += bh_s[2 * HC + jj];

            const float xr = xl_s[0 * 256 + tid];
            const float xz = xl_s[1 * 256 + tid];
            const float xnn = xl_s[2 * 256 + tid];

            const float r = 1.f / (1.f + __expf(-(xr + hr)));
            const float z = 1.f / (1.f + __expf(-(xz + hz)));
            const float n = tanhf(xnn + r * hn);

            const int bg = bbase + bb;
            const int hg = hbase + jj;
            const float hold = h_s[bb * HSZ + hg];
            const float hnew = (1.f - z) * n + z * hold;

            g_hbuf[(t + 1) & 1][(size_t)bg * HSZ + hg] = hnew;
            yout[((size_t)t * BATCH + bg) * HSZ + hg] = hnew;
            if (t == S_LEN - 1) hfin[(size_t)bg * HSZ + hg] = hnew;
        }
        group_bar(bc, &epoch);
    }
}

// =====================================================================
// kernel_launch
// =====================================================================
extern "C" void kernel_launch(void* const* d_in, const int* in_sizes, int n_in,
                              void* d_out, int out_size)
{
    (void)in_sizes; (void)n_in; (void)out_size;
    const float* x   = (const float*)d_in[0];
    const float* hx  = (const float*)d_in[1];
    const float* wih = (const float*)d_in[2];
    const float* whh = (const float*)d_in[3];
    const float* bih = (const float*)d_in[4];
    const float* bhh = (const float*)d_in[5];

    float* out    = (float*)d_out;                            // [S,B,H]
    float* hidden = out + (size_t)S_LEN * BATCH * HSZ;        // [L,B,H]

    float* xlin = nullptr; float* y1 = nullptr; unsigned* ctr = nullptr;
    cudaGetSymbolAddress((void**)&xlin, g_xlin);
    cudaGetSymbolAddress((void**)&y1,   g_y1);
    cudaGetSymbolAddress((void**)&ctr,  g_ctr);

    cudaFuncSetAttribute(gru_recurrent,
                         cudaFuncAttributeMaxDynamicSharedMemorySize, SMEM_BYTES);

    const dim3 gemm_grid(G3 / GBN, (S_LEN * BATCH) / GBM);

    // ---- layer 0 ----
    gemm_xproj_tf32<<<gemm_grid, 256>>>(x, wih, bih, xlin);
    cudaMemsetAsync(ctr, 0, 4 * 32 * sizeof(unsigned));
    gru_recurrent<<<NBLK, 256, SMEM_BYTES>>>(xlin, whh, bhh, hx, y1, hidden);

    // ---- layer 1 ----
    gemm_xproj_tf32<<<gemm_grid, 256>>>(y1, wih + (size_t)G3 * ISZ, bih + G3, xlin);
    cudaMemsetAsync(ctr, 0, 4 * 32 * sizeof(unsigned));
    gru_recurrent<<<NBLK, 256, SMEM_BYTES>>>(xlin, whh + (size_t)G3 * HSZ, bhh + G3,
                                             hx + (size_t)BATCH * HSZ,
                                             out, hidden + (size_t)BATCH * HSZ);
}

// round 7
// speedup vs baseline: 1.5162x; 1.5162x over previous
#include <cuda_runtime.h>
#include <math.h>

#define S_LEN   2048
#define BATCH   64
#define ISZ     512
#define HSZ     512
#define G3      1536
#define NLAYERS 2

// ---------------- device scratch (no cudaMalloc allowed) ----------------
__device__ float g_xlin[(size_t)S_LEN * BATCH * G3];   // per-layer input projections
__device__ float g_y1[(size_t)S_LEN * BATCH * HSZ];    // layer-0 outputs
__device__ float g_hbuf[2][BATCH * HSZ];               // ping-pong hidden state
__device__ unsigned int g_bar;                         // grid barrier counter

// ---------------- packed f32x2 helpers ----------------
typedef unsigned long long u64;

__device__ __forceinline__ u64 pk2(float lo, float hi) {
    u64 r; asm("mov.b64 %0, {%1, %2};" : "=l"(r) : "f"(lo), "f"(hi)); return r;
}
__device__ __forceinline__ void fma2(u64& d, u64 a, u64 b) {
    asm("fma.rn.f32x2 %0, %1, %2, %3;" : "=l"(d) : "l"(a), "l"(b), "l"(d));
}
__device__ __forceinline__ float2 upk2(u64 v) {
    float2 r; asm("mov.b64 {%0, %1}, %2;" : "=f"(r.x), "=f"(r.y) : "l"(v)); return r;
}

// ---------------- tf32 helpers ----------------
__device__ __forceinline__ float to_tf32(float x) {
    float r; asm("cvt.rna.tf32.f32 %0, %1;" : "=f"(r) : "f"(x)); return r;
}
__device__ __forceinline__ void mma_tf32(float* d, const unsigned* a, const unsigned* b) {
    asm("mma.sync.aligned.m16n8k8.row.col.f32.tf32.tf32.f32 "
        "{%0,%1,%2,%3}, {%4,%5,%6,%7}, {%8,%9}, {%0,%1,%2,%3};"
        : "+f"(d[0]), "+f"(d[1]), "+f"(d[2]), "+f"(d[3])
        : "r"(a[0]), "r"(a[1]), "r"(a[2]), "r"(a[3]), "r"(b[0]), "r"(b[1]));
}

// =====================================================================
// tf32 tensor-core GEMM: C[M,N] = A[M,K=512] * W[N,K=512]^T + bias[N]
// Block 128x128, 8 warps (2x4), warp tile 64x32, K staged 16, double buffer.
// __launch_bounds__(256,2): force 2 CTAs/SM so one block's MMA issue hides
// the other's __syncthreads / LDS-fragment latency.
// =====================================================================
#define GBM 128
#define GBN 128
#define GBK 16
#define GSTAGES (ISZ / GBK)   // 32
#define APAD 20               // padded row stride (floats); conflict-free frags

__global__ __launch_bounds__(256, 2) void gemm_xproj_tf32(
    const float* __restrict__ A, const float* __restrict__ W,
    const float* __restrict__ bias, float* __restrict__ C)
{
    __shared__ __align__(16) float As[2][GBM * APAD];
    __shared__ __align__(16) float Bs[2][GBN * APAD];

    const int bx = blockIdx.x;
    const int by = blockIdx.y;
    const int tid  = threadIdx.x;
    const int lane = tid & 31;
    const int wid  = tid >> 5;
    const int wm = wid & 1;
    const int wn = wid >> 1;
    const int g  = lane >> 2;
    const int t4 = lane & 3;

    const int lrow = tid >> 2;
    const int lc4  = (tid & 3) * 4;

    const float* Ab = A + ((size_t)by * GBM + lrow) * ISZ + lc4;
    const float* Wb = W + ((size_t)bx * GBN + lrow) * ISZ + lc4;

    float4 av[2], wv[2];

    av[0] = *(const float4*)(Ab);
    av[1] = *(const float4*)(Ab + (size_t)64 * ISZ);
    wv[0] = *(const float4*)(Wb);
    wv[1] = *(const float4*)(Wb + (size_t)64 * ISZ);
    {
        float* as0 = &As[0][lrow * APAD + lc4];
        float* bs0 = &Bs[0][lrow * APAD + lc4];
        as0[0] = to_tf32(av[0].x); as0[1] = to_tf32(av[0].y);
        as0[2] = to_tf32(av[0].z); as0[3] = to_tf32(av[0].w);
        as0[64 * APAD + 0] = to_tf32(av[1].x); as0[64 * APAD + 1] = to_tf32(av[1].y);
        as0[64 * APAD + 2] = to_tf32(av[1].z); as0[64 * APAD + 3] = to_tf32(av[1].w);
        bs0[0] = to_tf32(wv[0].x); bs0[1] = to_tf32(wv[0].y);
        bs0[2] = to_tf32(wv[0].z); bs0[3] = to_tf32(wv[0].w);
        bs0[64 * APAD + 0] = to_tf32(wv[1].x); bs0[64 * APAD + 1] = to_tf32(wv[1].y);
        bs0[64 * APAD + 2] = to_tf32(wv[1].z); bs0[64 * APAD + 3] = to_tf32(wv[1].w);
    }
    __syncthreads();

    float acc[4][4][4];
#pragma unroll
    for (int i = 0; i < 4; i++)
#pragma unroll
        for (int j = 0; j < 4; j++)
#pragma unroll
            for (int r = 0; r < 4; r++) acc[i][j][r] = 0.f;

    for (int s = 0; s < GSTAGES; s++) {
        const int cur = s & 1;
        if (s + 1 < GSTAGES) {
            const size_t ko = (size_t)(s + 1) * GBK;
            av[0] = *(const float4*)(Ab + ko);
            av[1] = *(const float4*)(Ab + (size_t)64 * ISZ + ko);
            wv[0] = *(const float4*)(Wb + ko);
            wv[1] = *(const float4*)(Wb + (size_t)64 * ISZ + ko);
        }

        const float* as = As[cur];
        const float* bs = Bs[cur];
#pragma unroll
        for (int kk = 0; kk < 2; kk++) {
            const int kb = kk * 8 + t4;
            unsigned af[4][4];
#pragma unroll
            for (int ms = 0; ms < 4; ms++) {
                const int r0 = (wm * 64 + ms * 16 + g) * APAD;
                af[ms][0] = __float_as_uint(as[r0 + kb]);
                af[ms][1] = __float_as_uint(as[r0 + 8 * APAD + kb]);
                af[ms][2] = __float_as_uint(as[r0 + kb + 4]);
                af[ms][3] = __float_as_uint(as[r0 + 8 * APAD + kb + 4]);
            }
#pragma unroll
            for (int ns = 0; ns < 4; ns++) {
                const int c0 = (wn * 32 + ns * 8 + g) * APAD;
                unsigned bf[2];
                bf[0] = __float_as_uint(bs[c0 + kb]);
                bf[1] = __float_as_uint(bs[c0 + kb + 4]);
#pragma unroll
                for (int ms = 0; ms < 4; ms++)
                    mma_tf32(acc[ms][ns], af[ms], bf);
            }
        }

        if (s + 1 < GSTAGES) {
            float* as1 = &As[cur ^ 1][lrow * APAD + lc4];
            float* bs1 = &Bs[cur ^ 1][lrow * APAD + lc4];
            as1[0] = to_tf32(av[0].x); as1[1] = to_tf32(av[0].y);
            as1[2] = to_tf32(av[0].z); as1[3] = to_tf32(av[0].w);
            as1[64 * APAD + 0] = to_tf32(av[1].x); as1[64 * APAD + 1] = to_tf32(av[1].y);
            as1[64 * APAD + 2] = to_tf32(av[1].z); as1[64 * APAD + 3] = to_tf32(av[1].w);
            bs1[0] = to_tf32(wv[0].x); bs1[1] = to_tf32(wv[0].y);
            bs1[2] = to_tf32(wv[0].z); bs1[3] = to_tf32(wv[0].w);
            bs1[64 * APAD + 0] = to_tf32(wv[1].x); bs1[64 * APAD + 1] = to_tf32(wv[1].y);
            bs1[64 * APAD + 2] = to_tf32(wv[1].z); bs1[64 * APAD + 3] = to_tf32(wv[1].w);
        }
        __syncthreads();
    }

    float bv[4][2];
#pragma unroll
    for (int ns = 0; ns < 4; ns++) {
        const int cn = bx * GBN + wn * 32 + ns * 8 + t4 * 2;
        bv[ns][0] = __ldg(&bias[cn]);
        bv[ns][1] = __ldg(&bias[cn + 1]);
    }
#pragma unroll
    for (int ms = 0; ms < 4; ms++) {
        const size_t r0 = (size_t)by * GBM + wm * 64 + ms * 16 + g;
#pragma unroll
        for (int ns = 0; ns < 4; ns++) {
            const int cn = bx * GBN + wn * 32 + ns * 8 + t4 * 2;
            float2 v0 = {acc[ms][ns][0] + bv[ns][0], acc[ms][ns][1] + bv[ns][1]};
            float2 v1 = {acc[ms][ns][2] + bv[ns][0], acc[ms][ns][3] + bv[ns][1]};
            *(float2*)(C + r0 * G3 + cn)       = v0;
            *(float2*)(C + (r0 + 8) * G3 + cn) = v1;
        }
    }
}

// =====================================================================
// Recurrent GRU kernel: persistent, 128 blocks (32 h-chunks x 4 b-chunks),
// W_hh register-resident (packed f32x2), SINGLE global atomic barrier per
// timestep (proven fastest in round 4 — do not decouple into groups).
// =====================================================================
#define HC   16
#define BC   16
#define NBLK ((HSZ / HC) * (BATCH / BC))   // 128
#define KSL  32
#define REDS 9

#define SM_HS   0                     // h_s[BC][HSZ]         = 8192
#define SM_RED  (BC * HSZ)            // red[256][3][REDS]    = 6912
#define SM_XL   (SM_RED + 256 * 3 * REDS)   // xl_s[3][256]   = 768
#define SM_BH   (SM_XL + 768)         // bh_s[3][HC]          = 48
#define SM_TOT  (SM_BH + 48)
#define SMEM_BYTES (SM_TOT * 4)

__device__ __forceinline__ void grid_bar(unsigned* epoch)
{
    __syncthreads();
    if (threadIdx.x == 0) {
        __threadfence();
        atomicAdd(&g_bar, 1u);
        const unsigned target = (++(*epoch)) * gridDim.x;
        volatile unsigned* p = &g_bar;
        while (*p < target) { }
        __threadfence();
    }
    __syncthreads();
}

__global__ __launch_bounds__(256, 1) void gru_recurrent(
    const float* __restrict__ xlin,
    const float* __restrict__ whh,
    const float* __restrict__ bhh,
    const float* __restrict__ hx,
    float* __restrict__ yout,
    float* __restrict__ hfin)
{
    extern __shared__ __align__(16) float sm[];
    float* h_s  = sm + SM_HS;
    float* red  = sm + SM_RED;
    float* xl_s = sm + SM_XL;
    float* bh_s = sm + SM_BH;

    const int blk = blockIdx.x;
    const int hc = blk >> 2;
    const int bc = blk & 3;
    const int hbase = hc * HC;
    const int bbase = bc * BC;
    const int tid  = threadIdx.x;
    const int j    = tid & 15;
    const int ks   = tid >> 4;
    const int lane = tid & 31;
    const int warp = tid >> 5;

    // W_hh slice into registers, packed pairs
    u64 wr2[KSL / 2], wz2[KSL / 2], wn2[KSL / 2];
    {
        const u64* rowr = (const u64*)(whh + (size_t)(0 * HSZ + hbase + j) * HSZ + ks * KSL);
        const u64* rowz = (const u64*)(whh + (size_t)(1 * HSZ + hbase + j) * HSZ + ks * KSL);
        const u64* rown = (const u64*)(whh + (size_t)(2 * HSZ + hbase + j) * HSZ + ks * KSL);
#pragma unroll
        for (int q = 0; q < KSL / 2; q++) {
            wr2[q] = rowr[q]; wz2[q] = rowz[q]; wn2[q] = rown[q];
        }
    }
    if (tid < HC) {
        bh_s[tid]          = bhh[0 * HSZ + hbase + tid];
        bh_s[HC + tid]     = bhh[1 * HSZ + hbase + tid];
        bh_s[2 * HC + tid] = bhh[2 * HSZ + hbase + tid];
    }

    // init hidden state (buffer 0) for this block's tile
    {
        const int jj = tid >> 4, bb = tid & 15;
        const size_t idx = (size_t)(bbase + bb) * HSZ + hbase + jj;
        g_hbuf[0][idx] = hx[idx];
    }
    unsigned epoch = 0;
    grid_bar(&epoch);

    // prefetch x_lin for t=0
    const int pbb = tid >> 4, pjj = tid & 15;
    const float* xpbase = xlin + ((size_t)(bbase + pbb)) * G3 + hbase + pjj;
    float xn[3];
#pragma unroll
    for (int gk = 0; gk < 3; gk++) xn[gk] = __ldg(xpbase + gk * HSZ);

    for (int t = 0; t < S_LEN; t++) {
        // commit prefetched x_lin; stage h
        {
#pragma unroll
            for (int gk = 0; gk < 3; gk++) xl_s[gk * 256 + tid] = xn[gk];

            const float4* src = (const float4*)(g_hbuf[t & 1] + (size_t)bbase * HSZ);
            float4* dst = (float4*)h_s;
#pragma unroll
            for (int r = 0; r < 8; r++)
                dst[tid + 256 * r] = __ldcg(src + tid + 256 * r);
        }
        __syncthreads();

        // matmul partials (FFMA2 over register W_hh)
#pragma unroll 2
        for (int b = 0; b < BC; b++) {
            u64 ar2 = 0ull, az2 = 0ull, an2 = 0ull;
            const ulonglong2* hp = (const ulonglong2*)(h_s + b * HSZ + ks * KSL);
#pragma unroll
            for (int q = 0; q < KSL / 4; q++) {
                ulonglong2 hv = hp[q];
                fma2(ar2, wr2[2*q],     hv.x);
                fma2(az2, wz2[2*q],     hv.x);
                fma2(an2, wn2[2*q],     hv.x);
                fma2(ar2, wr2[2*q + 1], hv.y);
                fma2(az2, wz2[2*q + 1], hv.y);
                fma2(an2, wn2[2*q + 1], hv.y);
            }
            float2 arf = upk2(ar2), azf = upk2(az2), anf = upk2(an2);
            float ar = arf.x + arf.y;
            float az = azf.x + azf.y;
            float an = anf.x + anf.y;
            ar += __shfl_xor_sync(0xffffffffu, ar, 16);
            az += __shfl_xor_sync(0xffffffffu, az, 16);
            an += __shfl_xor_sync(0xffffffffu, an, 16);
            if (lane < 16) {
                float* rb = red + ((b * HC + j) * 3) * REDS + warp;
                rb[0]        = ar;
                rb[REDS]     = az;
                rb[2 * REDS] = an;
            }
        }

        // prefetch x_lin for t+1 (overlaps reduction + barrier)
        if (t + 1 < S_LEN) {
            const float* xp = xpbase + (size_t)(t + 1) * BATCH * G3;
#pragma unroll
            for (int gk = 0; gk < 3; gk++) xn[gk] = __ldg(xp + gk * HSZ);
        }
        __syncthreads();

        // reduce, gates, update
        {
            const int jj = tid & 15;
            const int bb = tid >> 4;
            const float* rb = red + ((bb * HC + jj) * 3) * REDS;
            float hr = 0.f, hz = 0.f, hn = 0.f;
#pragma unroll
            for (int w = 0; w < 8; w++) {
                hr += rb[w]; hz += rb[REDS + w]; hn += rb[2 * REDS + w];
            }
            hr += bh_s[jj]; hz += bh_s[HC + jj]; hn += bh_s[2 * HC + jj];

            const float xr = xl_s[0 * 256 + tid];
            const float xz = xl_s[1 * 256 + tid];
            const float xnn = xl_s[2 * 256 + tid];

            const float r = 1.f / (1.f + __expf(-(xr + hr)));
            const float z = 1.f / (1.f + __expf(-(xz + hz)));
            const float n = tanhf(xnn + r * hn);

            const int bg = bbase + bb;
            const int hg = hbase + jj;
            const float hold = h_s[bb * HSZ + hg];
            const float hnew = (1.f - z) * n + z * hold;

            g_hbuf[(t + 1) & 1][(size_t)bg * HSZ + hg] = hnew;
            yout[((size_t)t * BATCH + bg) * HSZ + hg] = hnew;
            if (t == S_LEN - 1) hfin[(size_t)bg * HSZ + hg] = hnew;
        }
        grid_bar(&epoch);
    }
}

// =====================================================================
// kernel_launch
// =====================================================================
extern "C" void kernel_launch(void* const* d_in, const int* in_sizes, int n_in,
                              void* d_out, int out_size)
{
    (void)in_sizes; (void)n_in; (void)out_size;
    const float* x   = (const float*)d_in[0];
    const float* hx  = (const float*)d_in[1];
    const float* wih = (const float*)d_in[2];
    const float* whh = (const float*)d_in[3];
    const float* bih = (const float*)d_in[4];
    const float* bhh = (const float*)d_in[5];

    float* out    = (float*)d_out;                            // [S,B,H]
    float* hidden = out + (size_t)S_LEN * BATCH * HSZ;        // [L,B,H]

    float* xlin = nullptr; float* y1 = nullptr; unsigned* bar = nullptr;
    cudaGetSymbolAddress((void**)&xlin, g_xlin);
    cudaGetSymbolAddress((void**)&y1,   g_y1);
    cudaGetSymbolAddress((void**)&bar,  g_bar);

    cudaFuncSetAttribute(gru_recurrent,
                         cudaFuncAttributeMaxDynamicSharedMemorySize, SMEM_BYTES);

    const dim3 gemm_grid(G3 / GBN, (S_LEN * BATCH) / GBM);

    // ---- layer 0 ----
    gemm_xproj_tf32<<<gemm_grid, 256>>>(x, wih, bih, xlin);
    cudaMemsetAsync(bar, 0, sizeof(unsigned));
    gru_recurrent<<<NBLK, 256, SMEM_BYTES>>>(xlin, whh, bhh, hx, y1, hidden);

    // ---- layer 1 ----
    gemm_xproj_tf32<<<gemm_grid, 256>>>(y1, wih + (size_t)G3 * ISZ, bih + G3, xlin);
    cudaMemsetAsync(bar, 0, sizeof(unsigned));
    gru_recurrent<<<NBLK, 256, SMEM_BYTES>>>(xlin, whh + (size_t)G3 * HSZ, bhh + G3,
                                             hx + (size_t)BATCH * HSZ,
                                             out, hidden + (size_t)BATCH * HSZ);
}

// round 8
// speedup vs baseline: 1.8979x; 1.2517x over previous
#include <cuda_runtime.h>
#include <math.h>

#define S_LEN   2048
#define BATCH   64
#define ISZ     512
#define HSZ     512
#define G3      1536
#define NLAYERS 2

// ---------------- device scratch (no cudaMalloc allowed) ----------------
__device__ float g_xlin[(size_t)S_LEN * BATCH * G3];   // per-layer input projections
__device__ float g_y1[(size_t)S_LEN * BATCH * HSZ];    // layer-0 outputs
__device__ float g_hbuf[2][BATCH * HSZ];               // ping-pong hidden state
__device__ unsigned int g_bar;                         // grid barrier counter

// ---------------- tf32 helpers ----------------
__device__ __forceinline__ float to_tf32(float x) {
    float r; asm("cvt.rna.tf32.f32 %0, %1;" : "=f"(r) : "f"(x)); return r;
}
__device__ __forceinline__ void mma_tf32(float* d, const unsigned* a, const unsigned* b) {
    asm("mma.sync.aligned.m16n8k8.row.col.f32.tf32.tf32.f32 "
        "{%0,%1,%2,%3}, {%4,%5,%6,%7}, {%8,%9}, {%0,%1,%2,%3};"
        : "+f"(d[0]), "+f"(d[1]), "+f"(d[2]), "+f"(d[3])
        : "r"(a[0]), "r"(a[1]), "r"(a[2]), "r"(a[3]), "r"(b[0]), "r"(b[1]));
}

// =====================================================================
// tf32 tensor-core GEMM: C[M,N] = A[M,K=512] * W[N,K=512]^T + bias[N]
// Block 128x128, 8 warps (2x4), warp tile 64x32, K staged 16, double
// buffer, 2 CTAs/SM. (Proven config from round 7 — unchanged.)
// =====================================================================
#define GBM 128
#define GBN 128
#define GBK 16
#define GSTAGES (ISZ / GBK)   // 32
#define APAD 20

__global__ __launch_bounds__(256, 2) void gemm_xproj_tf32(
    const float* __restrict__ A, const float* __restrict__ W,
    const float* __restrict__ bias, float* __restrict__ C)
{
    __shared__ __align__(16) float As[2][GBM * APAD];
    __shared__ __align__(16) float Bs[2][GBN * APAD];

    const int bx = blockIdx.x;
    const int by = blockIdx.y;
    const int tid  = threadIdx.x;
    const int lane = tid & 31;
    const int wid  = tid >> 5;
    const int wm = wid & 1;
    const int wn = wid >> 1;
    const int g  = lane >> 2;
    const int t4 = lane & 3;

    const int lrow = tid >> 2;
    const int lc4  = (tid & 3) * 4;

    const float* Ab = A + ((size_t)by * GBM + lrow) * ISZ + lc4;
    const float* Wb = W + ((size_t)bx * GBN + lrow) * ISZ + lc4;

    float4 av[2], wv[2];

    av[0] = *(const float4*)(Ab);
    av[1] = *(const float4*)(Ab + (size_t)64 * ISZ);
    wv[0] = *(const float4*)(Wb);
    wv[1] = *(const float4*)(Wb + (size_t)64 * ISZ);
    {
        float* as0 = &As[0][lrow * APAD + lc4];
        float* bs0 = &Bs[0][lrow * APAD + lc4];
        as0[0] = to_tf32(av[0].x); as0[1] = to_tf32(av[0].y);
        as0[2] = to_tf32(av[0].z); as0[3] = to_tf32(av[0].w);
        as0[64 * APAD + 0] = to_tf32(av[1].x); as0[64 * APAD + 1] = to_tf32(av[1].y);
        as0[64 * APAD + 2] = to_tf32(av[1].z); as0[64 * APAD + 3] = to_tf32(av[1].w);
        bs0[0] = to_tf32(wv[0].x); bs0[1] = to_tf32(wv[0].y);
        bs0[2] = to_tf32(wv[0].z); bs0[3] = to_tf32(wv[0].w);
        bs0[64 * APAD + 0] = to_tf32(wv[1].x); bs0[64 * APAD + 1] = to_tf32(wv[1].y);
        bs0[64 * APAD + 2] = to_tf32(wv[1].z); bs0[64 * APAD + 3] = to_tf32(wv[1].w);
    }
    __syncthreads();

    float acc[4][4][4];
#pragma unroll
    for (int i = 0; i < 4; i++)
#pragma unroll
        for (int j = 0; j < 4; j++)
#pragma unroll
            for (int r = 0; r < 4; r++) acc[i][j][r] = 0.f;

    for (int s = 0; s < GSTAGES; s++) {
        const int cur = s & 1;
        if (s + 1 < GSTAGES) {
            const size_t ko = (size_t)(s + 1) * GBK;
            av[0] = *(const float4*)(Ab + ko);
            av[1] = *(const float4*)(Ab + (size_t)64 * ISZ + ko);
            wv[0] = *(const float4*)(Wb + ko);
            wv[1] = *(const float4*)(Wb + (size_t)64 * ISZ + ko);
        }

        const float* as = As[cur];
        const float* bs = Bs[cur];
#pragma unroll
        for (int kk = 0; kk < 2; kk++) {
            const int kb = kk * 8 + t4;
            unsigned af[4][4];
#pragma unroll
            for (int ms = 0; ms < 4; ms++) {
                const int r0 = (wm * 64 + ms * 16 + g) * APAD;
                af[ms][0] = __float_as_uint(as[r0 + kb]);
                af[ms][1] = __float_as_uint(as[r0 + 8 * APAD + kb]);
                af[ms][2] = __float_as_uint(as[r0 + kb + 4]);
                af[ms][3] = __float_as_uint(as[r0 + 8 * APAD + kb + 4]);
            }
#pragma unroll
            for (int ns = 0; ns < 4; ns++) {
                const int c0 = (wn * 32 + ns * 8 + g) * APAD;
                unsigned bf[2];
                bf[0] = __float_as_uint(bs[c0 + kb]);
                bf[1] = __float_as_uint(bs[c0 + kb + 4]);
#pragma unroll
                for (int ms = 0; ms < 4; ms++)
                    mma_tf32(acc[ms][ns], af[ms], bf);
            }
        }

        if (s + 1 < GSTAGES) {
            float* as1 = &As[cur ^ 1][lrow * APAD + lc4];
            float* bs1 = &Bs[cur ^ 1][lrow * APAD + lc4];
            as1[0] = to_tf32(av[0].x); as1[1] = to_tf32(av[0].y);
            as1[2] = to_tf32(av[0].z); as1[3] = to_tf32(av[0].w);
            as1[64 * APAD + 0] = to_tf32(av[1].x); as1[64 * APAD + 1] = to_tf32(av[1].y);
            as1[64 * APAD + 2] = to_tf32(av[1].z); as1[64 * APAD + 3] = to_tf32(av[1].w);
            bs1[0] = to_tf32(wv[0].x); bs1[1] = to_tf32(wv[0].y);
            bs1[2] = to_tf32(wv[0].z); bs1[3] = to_tf32(wv[0].w);
            bs1[64 * APAD + 0] = to_tf32(wv[1].x); bs1[64 * APAD + 1] = to_tf32(wv[1].y);
            bs1[64 * APAD + 2] = to_tf32(wv[1].z); bs1[64 * APAD + 3] = to_tf32(wv[1].w);
        }
        __syncthreads();
    }

    float bv[4][2];
#pragma unroll
    for (int ns = 0; ns < 4; ns++) {
        const int cn = bx * GBN + wn * 32 + ns * 8 + t4 * 2;
        bv[ns][0] = __ldg(&bias[cn]);
        bv[ns][1] = __ldg(&bias[cn + 1]);
    }
#pragma unroll
    for (int ms = 0; ms < 4; ms++) {
        const size_t r0 = (size_t)by * GBM + wm * 64 + ms * 16 + g;
#pragma unroll
        for (int ns = 0; ns < 4; ns++) {
            const int cn = bx * GBN + wn * 32 + ns * 8 + t4 * 2;
            float2 v0 = {acc[ms][ns][0] + bv[ns][0], acc[ms][ns][1] + bv[ns][1]};
            float2 v1 = {acc[ms][ns][2] + bv[ns][0], acc[ms][ns][3] + bv[ns][1]};
            *(float2*)(C + r0 * G3 + cn)       = v0;
            *(float2*)(C + (r0 + 8) * G3 + cn) = v1;
        }
    }
}

// =====================================================================
// Recurrent GRU kernel — TENSOR-CORE matmul version.
// 128 blocks (32 h-chunks x 4 b-chunks), 256 threads / 8 warps.
// Per step per block: C[16 batch][48 gate-out] = h[16][512] @ W^T.
// k-split across 8 warps (64 k each = 8 mma k-steps); W_hh held in regs
// as pre-built tf32 B-fragments (6 n-tiles x 8 k-steps x 2 regs = 96).
// h staged to smem tf32 (padded stride 516 -> conflict-free frag loads);
// carried state 'hold' read fp32 from gmem (no state quantization).
// Cross-warp reduce via smem (stride 9 -> conflict-free reads).
// Single global atomic barrier per step (proven fastest).
// =====================================================================
#define HC   16
#define BC   16
#define NBLK 128
#define HSP  516                      // padded h row stride (floats)

#define SM_HS   0                     // hs[16][HSP]          = 8256
#define SM_RED  (BC * HSP)            // red[16][48][9]       = 6912
#define SM_XL   (SM_RED + 768 * 9)    // xl_s[3][256]         = 768
#define SM_BH   (SM_XL + 768)         // bh_s[3][16]          = 48
#define SM_TOT  (SM_BH + 48)
#define SMEM_BYTES (SM_TOT * 4)

__device__ __forceinline__ void grid_bar(unsigned* epoch)
{
    __syncthreads();
    if (threadIdx.x == 0) {
        __threadfence();
        atomicAdd(&g_bar, 1u);
        const unsigned target = (++(*epoch)) * gridDim.x;
        volatile unsigned* p = &g_bar;
        while (*p < target) { }
        __threadfence();
    }
    __syncthreads();
}

__global__ __launch_bounds__(256, 1) void gru_recurrent(
    const float* __restrict__ xlin,
    const float* __restrict__ whh,
    const float* __restrict__ bhh,
    const float* __restrict__ hx,
    float* __restrict__ yout,
    float* __restrict__ hfin)
{
    extern __shared__ __align__(16) float sm[];
    float* hs   = sm + SM_HS;
    float* red  = sm + SM_RED;
    float* xl_s = sm + SM_XL;
    float* bh_s = sm + SM_BH;

    const int blk = blockIdx.x;
    const int hc = blk >> 2;          // 0..31
    const int bc = blk & 3;           // 0..3
    const int hbase = hc * HC;
    const int bbase = bc * BC;
    const int tid  = threadIdx.x;
    const int lane = tid & 31;
    const int warp = tid >> 5;        // k-slice: k in [warp*64, warp*64+64)
    const int gid  = lane >> 2;       // 0..7
    const int t4   = lane & 3;        // 0..3

    // ---- W_hh as register-resident tf32 B-fragments ----
    // n-tile nt covers out-cols nt*8..nt*8+7; out-col c: gate=c>>4, j=c&15.
    unsigned wb[6][8][2];
#pragma unroll
    for (int nt = 0; nt < 6; nt++) {
        const int c = nt * 8 + gid;
        const int gate = c >> 4, j = c & 15;
        const float* wrow = whh + (size_t)(gate * HSZ + hbase + j) * HSZ + warp * 64;
#pragma unroll
        for (int ks = 0; ks < 8; ks++) {
            wb[nt][ks][0] = __float_as_uint(to_tf32(wrow[ks * 8 + t4]));
            wb[nt][ks][1] = __float_as_uint(to_tf32(wrow[ks * 8 + t4 + 4]));
        }
    }
    if (tid < HC) {
        bh_s[tid]          = bhh[0 * HSZ + hbase + tid];
        bh_s[HC + tid]     = bhh[1 * HSZ + hbase + tid];
        bh_s[2 * HC + tid] = bhh[2 * HSZ + hbase + tid];
    }

    // init hidden state (buffer 0) for this block's tile
    {
        const int jj = tid >> 4, bb = tid & 15;
        const size_t idx = (size_t)(bbase + bb) * HSZ + hbase + jj;
        g_hbuf[0][idx] = hx[idx];
    }
    unsigned epoch = 0;
    grid_bar(&epoch);

    // prefetch x_lin for t=0
    const int pbb = tid >> 4, pjj = tid & 15;
    const float* xpbase = xlin + ((size_t)(bbase + pbb)) * G3 + hbase + pjj;
    float xn[3];
#pragma unroll
    for (int gk = 0; gk < 3; gk++) xn[gk] = __ldg(xpbase + gk * HSZ);

    for (int t = 0; t < S_LEN; t++) {
        const float* hsrc = g_hbuf[t & 1] + (size_t)bbase * HSZ;

        // ---- stage: commit x_lin; h -> tf32 smem (padded); hold -> reg ----
#pragma unroll
        for (int gk = 0; gk < 3; gk++) xl_s[gk * 256 + tid] = xn[gk];

#pragma unroll
        for (int r = 0; r < 8; r++) {
            const int e = tid + 256 * r;          // float4 index
            const int b = e >> 7;                 // batch row
            const int k = (e & 127) * 4;          // k offset
            float4 v = __ldcg((const float4*)hsrc + e);
            float4 c;
            c.x = to_tf32(v.x); c.y = to_tf32(v.y);
            c.z = to_tf32(v.z); c.w = to_tf32(v.w);
            *(float4*)(hs + b * HSP + k) = c;
        }
        const float hold = __ldcg(hsrc + (size_t)(tid >> 4) * HSZ + hbase + (tid & 15));
        __syncthreads();

        // ---- tensor-core matmul: 8 k-steps x 6 n-tiles per warp ----
        float cacc[6][4];
#pragma unroll
        for (int nt = 0; nt < 6; nt++)
#pragma unroll
            for (int r = 0; r < 4; r++) cacc[nt][r] = 0.f;

#pragma unroll
        for (int ks = 0; ks < 8; ks++) {
            const int k = warp * 64 + ks * 8 + t4;
            unsigned af[4];
            af[0] = __float_as_uint(hs[gid * HSP + k]);
            af[1] = __float_as_uint(hs[(gid + 8) * HSP + k]);
            af[2] = __float_as_uint(hs[gid * HSP + k + 4]);
            af[3] = __float_as_uint(hs[(gid + 8) * HSP + k + 4]);
#pragma unroll
            for (int nt = 0; nt < 6; nt++)
                mma_tf32(cacc[nt], af, wb[nt][ks]);
        }

        // ---- store k-partials to smem ----
#pragma unroll
        for (int nt = 0; nt < 6; nt++) {
            const int n0 = nt * 8 + t4 * 2;
            float* r0 = red + (gid * 48 + n0) * 9 + warp;
            float* r1 = red + ((gid + 8) * 48 + n0) * 9 + warp;
            r0[0] = cacc[nt][0]; r0[9] = cacc[nt][1];
            r1[0] = cacc[nt][2]; r1[9] = cacc[nt][3];
        }

        // prefetch x_lin for t+1 (overlaps reduction + barrier)
        if (t + 1 < S_LEN) {
            const float* xp = xpbase + (size_t)(t + 1) * BATCH * G3;
#pragma unroll
            for (int gk = 0; gk < 3; gk++) xn[gk] = __ldg(xp + gk * HSZ);
        }
        __syncthreads();

        // ---- reduce 8 warp-partials, gates, update ----
        {
            const int jj = tid & 15;   // h index
            const int bb = tid >> 4;   // batch
            float hsum[3];
#pragma unroll
            for (int gk = 0; gk < 3; gk++) {
                const float* rb = red + (bb * 48 + gk * 16 + jj) * 9;
                float s = 0.f;
#pragma unroll
                for (int w = 0; w < 8; w++) s += rb[w];
                hsum[gk] = s + bh_s[gk * HC + jj];
            }

            const float xr = xl_s[0 * 256 + tid];
            const float xz = xl_s[1 * 256 + tid];
            const float xnn = xl_s[2 * 256 + tid];

            const float r = 1.f / (1.f + __expf(-(xr + hsum[0])));
            const float z = 1.f / (1.f + __expf(-(xz + hsum[1])));
            const float n = tanhf(xnn + r * hsum[2]);

            const int bg = bbase + bb;
            const int hg = hbase + jj;
            const float hnew = (1.f - z) * n + z * hold;

            g_hbuf[(t + 1) & 1][(size_t)bg * HSZ + hg] = hnew;
            yout[((size_t)t * BATCH + bg) * HSZ + hg] = hnew;
            if (t == S_LEN - 1) hfin[(size_t)bg * HSZ + hg] = hnew;
        }
        grid_bar(&epoch);
    }
}

// =====================================================================
// kernel_launch
// =====================================================================
extern "C" void kernel_launch(void* const* d_in, const int* in_sizes, int n_in,
                              void* d_out, int out_size)
{
    (void)in_sizes; (void)n_in; (void)out_size;
    const float* x   = (const float*)d_in[0];
    const float* hx  = (const float*)d_in[1];
    const float* wih = (const float*)d_in[2];
    const float* whh = (const float*)d_in[3];
    const float* bih = (const float*)d_in[4];
    const float* bhh = (const float*)d_in[5];

    float* out    = (float*)d_out;                            // [S,B,H]
    float* hidden = out + (size_t)S_LEN * BATCH * HSZ;        // [L,B,H]

    float* xlin = nullptr; float* y1 = nullptr; unsigned* bar = nullptr;
    cudaGetSymbolAddress((void**)&xlin, g_xlin);
    cudaGetSymbolAddress((void**)&y1,   g_y1);
    cudaGetSymbolAddress((void**)&bar,  g_bar);

    cudaFuncSetAttribute(gru_recurrent,
                         cudaFuncAttributeMaxDynamicSharedMemorySize, SMEM_BYTES);

    const dim3 gemm_grid(G3 / GBN, (S_LEN * BATCH) / GBM);

    // ---- layer 0 ----
    gemm_xproj_tf32<<<gemm_grid, 256>>>(x, wih, bih, xlin);
    cudaMemsetAsync(bar, 0, sizeof(unsigned));
    gru_recurrent<<<NBLK, 256, SMEM_BYTES>>>(xlin, whh, bhh, hx, y1, hidden);

    // ---- layer 1 ----
    gemm_xproj_tf32<<<gemm_grid, 256>>>(y1, wih + (size_t)G3 * ISZ, bih + G3, xlin);
    cudaMemsetAsync(bar, 0, sizeof(unsigned));
    gru_recurrent<<<NBLK, 256, SMEM_BYTES>>>(xlin, whh + (size_t)G3 * HSZ, bhh + G3,
                                             hx + (size_t)BATCH * HSZ,
                                             out, hidden + (size_t)BATCH * HSZ);
}